// round 11
// baseline (speedup 1.0000x reference)
#include <cuda_runtime.h>
#include <cuda_bf16.h>
#include <math.h>

// ---- static problem config (matches reference) ----
#define N_ATOMS 16384
#define NUM_BATCH 32
#define ATOMS_PER_BATCH 512
#define N_PAIRS 1048576

#define ALPHA_F       0.401f            // 4/10 + 0.001
#define K2FAC_F       1.5547167f        // 0.25 / ALPHA^2
#define TWO_PI_F      6.283185307179586f
#define SELF_F        0.2262400229976503f   // ALPHA / sqrt(pi)
#define EPS_F         1e-8f
#define FULL 0xFFFFFFFFu

#define REAL_BLOCKS 256                 // 256 blocks * 8 warps * 512 pairs = 1M
#define PAIRS_PER_WARP 512
#define KMAXI 8

// ------------------------------------------------------------------
// Compile-time canonical half of the k lattice (KMAX=8 is static).
// canonical: mx>0 | (mx=0 & my>0) | (mx=0 & my=0 & mz>0); 0<|k|^2<=64.
// ------------------------------------------------------------------
struct alignas(16) KEntry { float x, y, z, w; };

constexpr int count_khalf() {
    int n = 0;
    for (int mx = -KMAXI; mx <= KMAXI; mx++)
        for (int my = -KMAXI; my <= KMAXI; my++)
            for (int mz = -KMAXI; mz <= KMAXI; mz++) {
                int k2 = mx * mx + my * my + mz * mz;
                if (k2 == 0 || k2 > KMAXI * KMAXI) continue;
                if ((mx > 0) || (mx == 0 && (my > 0 || (my == 0 && mz > 0)))) n++;
            }
    return n;
}
constexpr int NK   = count_khalf();
constexpr int KB   = (NK + 31) / 32;     // number of 32-k chunks
constexpr int KPAD = KB * 32;
// balanced chunk-group count (KB=33 -> 11 groups of exactly 3 chunks)
constexpr int JG   = (KB % 8 == 0) ? 8 : (KB % 11 == 0) ? 11
                   : (KB % 9 == 0) ? 9 : (KB % 7 == 0) ? 7 : 8;

struct KTable { KEntry e[KPAD]; };

constexpr KTable make_ktable() {
    KTable t{};
    int n = 0;
    for (int mx = -KMAXI; mx <= KMAXI; mx++)
        for (int my = -KMAXI; my <= KMAXI; my++)
            for (int mz = -KMAXI; mz <= KMAXI; mz++) {
                int k2 = mx * mx + my * my + mz * mz;
                if (k2 == 0 || k2 > KMAXI * KMAXI) continue;
                if (!((mx > 0) || (mx == 0 && (my > 0 || (my == 0 && mz > 0))))) continue;
                t.e[n].x = (float)mx; t.e[n].y = (float)my;
                t.e[n].z = (float)mz; t.e[n].w = 2.0f;    // +k and -k
                n++;
            }
    for (; n < KPAD; n++) { t.e[n].x = 1.0f; t.e[n].y = 0.0f; t.e[n].z = 0.0f; t.e[n].w = 0.0f; }
    return t;
}
constexpr KTable h_ktable = make_ktable();
__constant__ KTable c_kt = h_ktable;

#define WNORM_BLOCKS 32
#define RECIP_BASE   (REAL_BLOCKS + WNORM_BLOCKS)
#define RECIP_BLOCKS (NUM_BATCH * JG)
#define TOTAL_BLOCKS (RECIP_BASE + RECIP_BLOCKS)
#define NPART        (JG * 8 * NUM_BATCH)   // one partial per (group, warp, batch)
#define PPB          (JG * 8)               // partials per batch

// scratch (no allocations). Partials/wnorm are overwritten every call;
// g_ereal and g_ctr are restored to zero by the finalizing block so
// every graph replay starts from a clean state.
__device__ float  g_recip_part[NPART];
__device__ float  g_wnorm[NUM_BATCH];
__device__ float4 g_ereal4[N_ATOMS / 4];
__device__ int    g_ctr;

// ------------------------------------------------------------------
// single fused kernel:
//   blocks [0, 256)        real space (coalesced pairs, warp segscan)
//   blocks [256, 288)      per-batch wnorm
//   blocks [288, 288+32*JG) recip: (batch b, group j); stage atoms once,
//                          loop 3 balanced k-chunks of 32 k (8 warps x 4 k)
// then: threadfence + ticket; the LAST block reduces recip partials to
// per-batch coefficients and does the elementwise finalize (float4),
// resetting scratch for the next graph replay.
// ------------------------------------------------------------------
__global__ void __launch_bounds__(256) k_main(
        const float* __restrict__ Qa,
        const float* __restrict__ rij,
        const int*   __restrict__ idx_i,
        const int*   __restrict__ idx_j,
        const float* __restrict__ R,
        const float* __restrict__ cell,
        float* __restrict__ out) {
    int bid = blockIdx.x;
    int tid = threadIdx.x;
    int warp = tid >> 5;
    int lane = tid & 31;

    __shared__ float4 s4[ATOMS_PER_BATCH];   // recip staging (8 KB)
    __shared__ float  sw[8];
    __shared__ float  scoef[NUM_BATCH];
    __shared__ int    s_last;

    float* g_ereal = (float*)g_ereal4;

    if (bid < REAL_BLOCKS) {
        // ---------------- real space ----------------
        int gw = bid * 8 + warp;
        int base = gw * PAIRS_PER_WARP;
#pragma unroll 2
        for (int it = 0; it < PAIRS_PER_WARP / 32; it++) {
            int p = base + it * 32 + lane;          // coalesced
            int ii = idx_i[p];
            int jj = idx_j[p];
            float rr = rij[p];
            float fac = __ldg(&Qa[ii]) * __ldg(&Qa[jj]);

            // C-inf switch, fast path
            float x = (rr - 2.5f) * 0.2f;
            float f;
            if (x <= 0.0f)      f = 1.0f;
            else if (x >= 1.0f) f = 0.0f;
            else {
                float fp = __expf(-__frcp_rn(x));
                float fm = __expf(-__frcp_rn(1.0f - x));
                f = fm * __frcp_rn(fp + fm);
            }
            float damped = rsqrtf(fmaf(rr, rr, 1.0f));
            float coul = __frcp_rn(rr);

            // erfc via Abramowitz-Stegun 7.1.26 (abs err <= 1.5e-7)
            float xa = ALPHA_F * rr;
            float t = __frcp_rn(fmaf(0.3275911f, xa, 1.0f));
            float poly = t * fmaf(t, fmaf(t, fmaf(t, fmaf(t, 1.061405429f,
                                -1.453152027f), 1.421413741f),
                                -0.284496736f), 0.254829592f);
            float er = poly * __expf(-xa * xa);

            float pw = fac * (f * damped + (1.0f - f) * coul) * er;

            // warp segmented reduction over sorted ii
            int prev = __shfl_up_sync(FULL, ii, 1);
            bool head = (lane == 0) || (ii != prev);
            unsigned hm = __ballot_sync(FULL, head);
            unsigned below = hm & (0xFFFFFFFFu >> (31 - lane));
            int hp = 31 - __clz(below);
            float s = pw;
#pragma unroll
            for (int d = 1; d < 32; d <<= 1) {
                float v = __shfl_up_sync(FULL, s, d);
                if (lane >= hp + d) s += v;
            }
            bool lastv = (lane == 31) || ((hm >> (lane + 1)) & 1u);
            if (lastv) atomicAdd(&g_ereal[ii], s);
        }
    } else if (bid < RECIP_BASE) {
        // ---------------- per-batch wnorm (overwrite) ----------------
        int b = bid - REAL_BLOCKS;
        float acc = 0.0f;
        for (int a = tid; a < ATOMS_PER_BATCH; a += 256) {
            float q = Qa[b * ATOMS_PER_BATCH + a];
            acc = fmaf(q, q, acc + EPS_F);
        }
#pragma unroll
        for (int o = 16; o > 0; o >>= 1) acc += __shfl_down_sync(FULL, acc, o);
        if (lane == 0) sw[warp] = acc;
        __syncthreads();
        if (tid == 0) {
            float tot = 0.0f;
#pragma unroll
            for (int w2 = 0; w2 < 8; w2++) tot += sw[w2];
            g_wnorm[b] = tot;
        }
    } else {
        // ---------------- reciprocal space ----------------
        int idx = bid - RECIP_BASE;
        int b = idx & (NUM_BATCH - 1);          // batch
        int j = idx >> 5;                       // chunk group 0..JG-1

        float ax = TWO_PI_F * __frcp_rn(cell[b * 9 + 0]);
        float ay = TWO_PI_F * __frcp_rn(cell[b * 9 + 4]);
        float az = TWO_PI_F * __frcp_rn(cell[b * 9 + 8]);

        for (int a = tid; a < ATOMS_PER_BATCH; a += 256) {
            int n = b * ATOMS_PER_BATCH + a;
            float4 v;
            v.x = R[n * 3 + 0] * ax;
            v.y = R[n * 3 + 1] * ay;
            v.z = R[n * 3 + 2] * az;
            v.w = Qa[n];
            s4[a] = v;
        }
        __syncthreads();

        const float4* kt = reinterpret_cast<const float4*>(c_kt.e);
        float blockAcc = 0.0f;                  // lane0 accumulator across chunks

        for (int chunk = j; chunk < KB; chunk += JG) {
            int kk = chunk * 32 + warp * 4;     // 4 k-vectors per warp
            float4 k0 = kt[kk + 0];
            float4 k1 = kt[kk + 1];
            float4 k2v = kt[kk + 2];
            float4 k3 = kt[kk + 3];

            float cr0 = 0.f, ci0 = 0.f, cr1 = 0.f, ci1 = 0.f;
            float cr2 = 0.f, ci2 = 0.f, cr3 = 0.f, ci3 = 0.f;

#pragma unroll 4
            for (int a = lane; a < ATOMS_PER_BATCH; a += 32) {
                float4 v = s4[a];
                float q = v.w;
                float d0 = fmaf(k0.x, v.x, fmaf(k0.y, v.y, k0.z * v.z));
                float d1 = fmaf(k1.x, v.x, fmaf(k1.y, v.y, k1.z * v.z));
                float d2 = fmaf(k2v.x, v.x, fmaf(k2v.y, v.y, k2v.z * v.z));
                float d3 = fmaf(k3.x, v.x, fmaf(k3.y, v.y, k3.z * v.z));
                float s0, c0, s1, c1, s2, c2, s3, c3;
                __sincosf(d0, &s0, &c0);
                __sincosf(d1, &s1, &c1);
                __sincosf(d2, &s2, &c2);
                __sincosf(d3, &s3, &c3);
                cr0 = fmaf(q, c0, cr0); ci0 = fmaf(q, s0, ci0);
                cr1 = fmaf(q, c1, cr1); ci1 = fmaf(q, s1, ci1);
                cr2 = fmaf(q, c2, cr2); ci2 = fmaf(q, s2, ci2);
                cr3 = fmaf(q, c3, cr3); ci3 = fmaf(q, s3, ci3);
            }
#pragma unroll
            for (int o = 16; o > 0; o >>= 1) {
                cr0 += __shfl_down_sync(FULL, cr0, o);
                ci0 += __shfl_down_sync(FULL, ci0, o);
                cr1 += __shfl_down_sync(FULL, cr1, o);
                ci1 += __shfl_down_sync(FULL, ci1, o);
                cr2 += __shfl_down_sync(FULL, cr2, o);
                ci2 += __shfl_down_sync(FULL, ci2, o);
                cr3 += __shfl_down_sync(FULL, cr3, o);
                ci3 += __shfl_down_sync(FULL, ci3, o);
            }
            if (lane == 0) {
                float kx, ky, kz, kk2, qg;
                kx = k0.x * ax; ky = k0.y * ay; kz = k0.z * az;
                kk2 = kx * kx + ky * ky + kz * kz;
                qg = __expf(-K2FAC_F * kk2) * __frcp_rn(kk2);
                blockAcc = fmaf(k0.w * qg, fmaf(cr0, cr0, ci0 * ci0), blockAcc);
                kx = k1.x * ax; ky = k1.y * ay; kz = k1.z * az;
                kk2 = kx * kx + ky * ky + kz * kz;
                qg = __expf(-K2FAC_F * kk2) * __frcp_rn(kk2);
                blockAcc = fmaf(k1.w * qg, fmaf(cr1, cr1, ci1 * ci1), blockAcc);
                kx = k2v.x * ax; ky = k2v.y * ay; kz = k2v.z * az;
                kk2 = kx * kx + ky * ky + kz * kz;
                qg = __expf(-K2FAC_F * kk2) * __frcp_rn(kk2);
                blockAcc = fmaf(k2v.w * qg, fmaf(cr2, cr2, ci2 * ci2), blockAcc);
                kx = k3.x * ax; ky = k3.y * ay; kz = k3.z * az;
                kk2 = kx * kx + ky * ky + kz * kz;
                qg = __expf(-K2FAC_F * kk2) * __frcp_rn(kk2);
                blockAcc = fmaf(k3.w * qg, fmaf(cr3, cr3, ci3 * ci3), blockAcc);
            }
        }
        if (lane == 0)
            g_recip_part[(j * 8 + warp) * NUM_BATCH + b] = blockAcc;   // plain store
    }

    // ------------- grid-wide completion ticket -------------
    __threadfence();                 // publish this thread's global writes
    __syncthreads();                 // all block threads' writes precede ticket
    if (tid == 0) {
        int t = atomicAdd(&g_ctr, 1);
        s_last = (t == TOTAL_BLOCKS - 1);
    }
    __syncthreads();
    if (!s_last) return;

    // ------------- finalize (last block only; all writers done) -------------
    __threadfence();                 // acquire side

    // per-batch coefficient: coef[b] = 2pi/vol * recip_sum / wnorm
    {
        int b = tid >> 3;            // 32 batches x 8 slots
        int slot = tid & 7;
        float t = 0.0f;
        for (int p = slot; p < PPB; p += 8)
            t += __ldcg(&g_recip_part[p * NUM_BATCH + b]);
#pragma unroll
        for (int o = 4; o > 0; o >>= 1) t += __shfl_down_sync(FULL, t, o, 8);
        if (slot == 0) {
            float Lx = cell[b * 9 + 0];
            float Ly = cell[b * 9 + 4];
            float Lz = cell[b * 9 + 8];
            float wn = __ldcg(&g_wnorm[b]);
            scoef[b] = t * TWO_PI_F * __frcp_rn(Lx * Ly * Lz) * __frcp_rn(wn);
        }
    }
    __syncthreads();

    // elementwise combine + scratch reset (float4, 16 iters/thread)
    const float4* qa4 = reinterpret_cast<const float4*>(Qa);
    float4* out4 = reinterpret_cast<float4*>(out);
    const float4 z4 = make_float4(0.f, 0.f, 0.f, 0.f);
#pragma unroll 4
    for (int i = tid; i < N_ATOMS / 4; i += 256) {
        float4 er = __ldcg(&g_ereal4[i]);
        float4 q  = qa4[i];
        float coef = scoef[i >> 7];          // 128 float4 per batch
        float4 o;
        o.x = er.x + (q.x * q.x + EPS_F) * coef - SELF_F * q.x * q.x;
        o.y = er.y + (q.y * q.y + EPS_F) * coef - SELF_F * q.y * q.y;
        o.z = er.z + (q.z * q.z + EPS_F) * coef - SELF_F * q.z * q.z;
        o.w = er.w + (q.w * q.w + EPS_F) * coef - SELF_F * q.w * q.w;
        out4[i] = o;
        g_ereal4[i] = z4;                    // restore zero invariant
    }
    if (tid == 0) g_ctr = 0;                 // restore counter for next replay
}

// ------------------------------------------------------------------
extern "C" void kernel_launch(void* const* d_in, const int* in_sizes, int n_in,
                              void* d_out, int out_size) {
    const float* Qa    = (const float*)d_in[0];
    const float* rij   = (const float*)d_in[1];
    const float* R     = (const float*)d_in[2];
    const float* cell  = (const float*)d_in[3];
    const int*   idx_i = (const int*)d_in[5];
    const int*   idx_j = (const int*)d_in[6];
    float* out = (float*)d_out;

    k_main<<<TOTAL_BLOCKS, 256>>>(Qa, rij, idx_i, idx_j, R, cell, out);
}

// round 13
// speedup vs baseline: 1.3602x; 1.3602x over previous
#include <cuda_runtime.h>
#include <cuda_bf16.h>
#include <math.h>

// ---- static problem config (matches reference) ----
#define N_ATOMS 16384
#define NUM_BATCH 32
#define ATOMS_PER_BATCH 512
#define N_PAIRS 1048576

#define ALPHA_F       0.401f            // 4/10 + 0.001
#define K2FAC_F       1.5547167f        // 0.25 / ALPHA^2
#define TWO_PI_F      6.283185307179586f
#define SELF_F        0.2262400229976503f   // ALPHA / sqrt(pi)
#define EPS_F         1e-8f
#define FULL 0xFFFFFFFFu

#define REAL_BLOCKS 256                 // 256 blocks * 8 warps * 512 pairs = 1M
#define PAIRS_PER_WARP 512
#define KMAXI 8

// ------------------------------------------------------------------
// Compile-time k-table organized as GROUPS of 4 consecutive mz within
// one (mx,my) column of the canonical half lattice. A warp computes one
// sincos for the first entry of a group and derives the other three by
// complex rotation with the per-atom phasor e^{i*theta_z}.
// canonical: mx>0 | (mx=0 & my>0) | (mx=0 & my=0 & mz>0); 0<|k|^2<=64.
// ------------------------------------------------------------------
struct KGroup { float mx, my, mz0, pad, w0, w1, w2, w3; };

constexpr int ifsqrt(int v) { int r = 0; while ((r + 1) * (r + 1) <= v) r++; return r; }

constexpr int count_groups() {
    int n = 0;
    n += 2;                                        // (0,0): mz 1..8 -> 2 groups
    for (int my = 1; my <= KMAXI; my++) {          // mx=0 columns
        int L = ifsqrt(KMAXI * KMAXI - my * my);
        n += (2 * L + 1 + 3) / 4;
    }
    for (int mx = 1; mx <= KMAXI; mx++) {
        int L2 = ifsqrt(KMAXI * KMAXI - mx * mx);
        for (int my = -L2; my <= L2; my++) {
            int L = ifsqrt(KMAXI * KMAXI - mx * mx - my * my);
            n += (2 * L + 1 + 3) / 4;
        }
    }
    return n;
}
constexpr int NG     = count_groups();
constexpr int NG_PAD = ((NG + 63) / 64) * 64;      // multiple of 64 -> KBg mult of 8
constexpr int KBg    = NG_PAD / 8;                 // chunks of 8 groups
constexpr int JG     = 8;                          // chunk groups per batch
static_assert(KBg % JG == 0, "balanced chunks");
constexpr int CHUNKS_PER_BLOCK = KBg / JG;

struct KGTable { KGroup g[NG_PAD]; };

constexpr KGTable make_kg() {
    KGTable t{};
    int n = 0;
    // helper lambda-free column emit
    // (0,0): mz 1..8
    for (int mz0 = 1; mz0 <= 8; mz0 += 4) {
        t.g[n].mx = 0.f; t.g[n].my = 0.f; t.g[n].mz0 = (float)mz0; t.g[n].pad = 0.f;
        t.g[n].w0 = (mz0 + 0 <= 8) ? 2.f : 0.f;
        t.g[n].w1 = (mz0 + 1 <= 8) ? 2.f : 0.f;
        t.g[n].w2 = (mz0 + 2 <= 8) ? 2.f : 0.f;
        t.g[n].w3 = (mz0 + 3 <= 8) ? 2.f : 0.f;
        n++;
    }
    for (int my = 1; my <= KMAXI; my++) {
        int L = ifsqrt(KMAXI * KMAXI - my * my);
        for (int mz0 = -L; mz0 <= L; mz0 += 4) {
            t.g[n].mx = 0.f; t.g[n].my = (float)my; t.g[n].mz0 = (float)mz0; t.g[n].pad = 0.f;
            t.g[n].w0 = (mz0 + 0 <= L) ? 2.f : 0.f;
            t.g[n].w1 = (mz0 + 1 <= L) ? 2.f : 0.f;
            t.g[n].w2 = (mz0 + 2 <= L) ? 2.f : 0.f;
            t.g[n].w3 = (mz0 + 3 <= L) ? 2.f : 0.f;
            n++;
        }
    }
    for (int mx = 1; mx <= KMAXI; mx++) {
        int L2 = ifsqrt(KMAXI * KMAXI - mx * mx);
        for (int my = -L2; my <= L2; my++) {
            int L = ifsqrt(KMAXI * KMAXI - mx * mx - my * my);
            for (int mz0 = -L; mz0 <= L; mz0 += 4) {
                t.g[n].mx = (float)mx; t.g[n].my = (float)my; t.g[n].mz0 = (float)mz0; t.g[n].pad = 0.f;
                t.g[n].w0 = (mz0 + 0 <= L) ? 2.f : 0.f;
                t.g[n].w1 = (mz0 + 1 <= L) ? 2.f : 0.f;
                t.g[n].w2 = (mz0 + 2 <= L) ? 2.f : 0.f;
                t.g[n].w3 = (mz0 + 3 <= L) ? 2.f : 0.f;
                n++;
            }
        }
    }
    // padding groups: weight 0, k2 > 0 for all 4 entries
    for (; n < NG_PAD; n++) {
        t.g[n].mx = 1.f; t.g[n].my = 0.f; t.g[n].mz0 = 0.f; t.g[n].pad = 0.f;
        t.g[n].w0 = 0.f; t.g[n].w1 = 0.f; t.g[n].w2 = 0.f; t.g[n].w3 = 0.f;
    }
    return t;
}
constexpr KGTable h_kg = make_kg();
__constant__ KGTable c_kg = h_kg;

#define WNORM_BLOCKS 32
#define RECIP_BASE   (REAL_BLOCKS + WNORM_BLOCKS)
#define RECIP_BLOCKS (NUM_BATCH * JG)
#define TOTAL_BLOCKS (RECIP_BASE + RECIP_BLOCKS)
#define PPB          (JG * 8)               // partials per batch (64)
#define NPART        (PPB * NUM_BATCH)

// scratch (no allocations). Partials/wnorm overwritten every call;
// g_ereal reset by its reader in k_final (zero invariant for replays).
__device__ float g_recip_part[NPART];
__device__ float g_wnorm[NUM_BATCH];
__device__ float g_ereal[N_ATOMS];

// ------------------------------------------------------------------
// fused main:
//   blocks [0, 256)        real space (coalesced pairs, warp segscan)
//   blocks [256, 288)      per-batch wnorm
//   blocks [288, 288+256)  recip: (batch b, group j). Stage 512 atoms as
//     (tx,ty,tz,q) + phasor (cos tz, sin tz) in SMEM once; loop 5 chunks.
//     Each warp: one k-GROUP per chunk -> 1 sincos + 3 rotations per atom.
// ------------------------------------------------------------------
__global__ void __launch_bounds__(256) k_main(
        const float* __restrict__ Qa,
        const float* __restrict__ rij,
        const int*   __restrict__ idx_i,
        const int*   __restrict__ idx_j,
        const float* __restrict__ R,
        const float* __restrict__ cell) {
    int bid = blockIdx.x;
    int tid = threadIdx.x;
    int warp = tid >> 5;
    int lane = tid & 31;

    if (bid < REAL_BLOCKS) {
        // ---------------- real space ----------------
        int gw = bid * 8 + warp;
        int base = gw * PAIRS_PER_WARP;
#pragma unroll 2
        for (int it = 0; it < PAIRS_PER_WARP / 32; it++) {
            int p = base + it * 32 + lane;          // coalesced
            int ii = idx_i[p];
            int jj = idx_j[p];
            float rr = rij[p];
            float fac = __ldg(&Qa[ii]) * __ldg(&Qa[jj]);

            // C-inf switch, fast path
            float x = (rr - 2.5f) * 0.2f;
            float f;
            if (x <= 0.0f)      f = 1.0f;
            else if (x >= 1.0f) f = 0.0f;
            else {
                float fp = __expf(-__frcp_rn(x));
                float fm = __expf(-__frcp_rn(1.0f - x));
                f = fm * __frcp_rn(fp + fm);
            }
            float damped = rsqrtf(fmaf(rr, rr, 1.0f));
            float coul = __frcp_rn(rr);

            // erfc via Abramowitz-Stegun 7.1.26 (abs err <= 1.5e-7)
            float xa = ALPHA_F * rr;
            float t = __frcp_rn(fmaf(0.3275911f, xa, 1.0f));
            float poly = t * fmaf(t, fmaf(t, fmaf(t, fmaf(t, 1.061405429f,
                                -1.453152027f), 1.421413741f),
                                -0.284496736f), 0.254829592f);
            float er = poly * __expf(-xa * xa);

            float pw = fac * (f * damped + (1.0f - f) * coul) * er;

            // warp segmented reduction over sorted ii
            int prev = __shfl_up_sync(FULL, ii, 1);
            bool head = (lane == 0) || (ii != prev);
            unsigned hm = __ballot_sync(FULL, head);
            unsigned below = hm & (0xFFFFFFFFu >> (31 - lane));
            int hp = 31 - __clz(below);
            float s = pw;
#pragma unroll
            for (int d = 1; d < 32; d <<= 1) {
                float v = __shfl_up_sync(FULL, s, d);
                if (lane >= hp + d) s += v;
            }
            bool lastv = (lane == 31) || ((hm >> (lane + 1)) & 1u);
            if (lastv) atomicAdd(&g_ereal[ii], s);
        }
    } else if (bid < RECIP_BASE) {
        // ---------------- per-batch wnorm (overwrite) ----------------
        int b = bid - REAL_BLOCKS;
        __shared__ float sw[8];
        float acc = 0.0f;
        for (int a = tid; a < ATOMS_PER_BATCH; a += 256) {
            float q = Qa[b * ATOMS_PER_BATCH + a];
            acc = fmaf(q, q, acc + EPS_F);
        }
#pragma unroll
        for (int o = 16; o > 0; o >>= 1) acc += __shfl_down_sync(FULL, acc, o);
        if (lane == 0) sw[warp] = acc;
        __syncthreads();
        if (tid == 0) {
            float tot = 0.0f;
#pragma unroll
            for (int w2 = 0; w2 < 8; w2++) tot += sw[w2];
            g_wnorm[b] = tot;
        }
    } else {
        // ---------------- reciprocal space (column recursion) ----------------
        int idx = bid - RECIP_BASE;
        int b = idx & (NUM_BATCH - 1);          // batch
        int j = idx >> 5;                       // chunk group 0..JG-1

        __shared__ float4 sA[ATOMS_PER_BATCH];  // (tx, ty, tz, q)
        __shared__ float2 sE[ATOMS_PER_BATCH];  // (cos tz, sin tz)

        float ax = TWO_PI_F * __frcp_rn(cell[b * 9 + 0]);
        float ay = TWO_PI_F * __frcp_rn(cell[b * 9 + 4]);
        float az = TWO_PI_F * __frcp_rn(cell[b * 9 + 8]);

        for (int a = tid; a < ATOMS_PER_BATCH; a += 256) {
            int n = b * ATOMS_PER_BATCH + a;
            float4 v;
            v.x = R[n * 3 + 0] * ax;
            v.y = R[n * 3 + 1] * ay;
            v.z = R[n * 3 + 2] * az;
            v.w = Qa[n];
            sA[a] = v;
            float cz, sz;
            __sincosf(v.z, &sz, &cz);
            sE[a] = make_float2(cz, sz);
        }
        __syncthreads();

        float blockAcc = 0.0f;                  // lane0 accumulator across chunks

#pragma unroll
        for (int c = 0; c < CHUNKS_PER_BLOCK; c++) {
            int grp = (j + c * JG) * 8 + warp;  // one group per warp per chunk
            const KGroup& G = c_kg.g[grp];
            float mx = G.mx, my = G.my, mz0 = G.mz0;

            float cr0 = 0.f, ci0 = 0.f, cr1 = 0.f, ci1 = 0.f;
            float cr2 = 0.f, ci2 = 0.f, cr3 = 0.f, ci3 = 0.f;

#pragma unroll 4
            for (int a = lane; a < ATOMS_PER_BATCH; a += 32) {
                float4 v = sA[a];
                float2 ez = sE[a];
                float q = v.w;
                float dxy = fmaf(mx, v.x, my * v.y);
                float d0 = fmaf(mz0, v.z, dxy);
                float s0, c0;
                __sincosf(d0, &s0, &c0);
                cr0 = fmaf(q, c0, cr0); ci0 = fmaf(q, s0, ci0);
                float c1 = fmaf(c0, ez.x, -s0 * ez.y);
                float s1 = fmaf(s0, ez.x,  c0 * ez.y);
                cr1 = fmaf(q, c1, cr1); ci1 = fmaf(q, s1, ci1);
                float c2 = fmaf(c1, ez.x, -s1 * ez.y);
                float s2 = fmaf(s1, ez.x,  c1 * ez.y);
                cr2 = fmaf(q, c2, cr2); ci2 = fmaf(q, s2, ci2);
                float c3 = fmaf(c2, ez.x, -s2 * ez.y);
                float s3 = fmaf(s2, ez.x,  c2 * ez.y);
                cr3 = fmaf(q, c3, cr3); ci3 = fmaf(q, s3, ci3);
            }
#pragma unroll
            for (int o = 16; o > 0; o >>= 1) {
                cr0 += __shfl_down_sync(FULL, cr0, o);
                ci0 += __shfl_down_sync(FULL, ci0, o);
                cr1 += __shfl_down_sync(FULL, cr1, o);
                ci1 += __shfl_down_sync(FULL, ci1, o);
                cr2 += __shfl_down_sync(FULL, cr2, o);
                ci2 += __shfl_down_sync(FULL, ci2, o);
                cr3 += __shfl_down_sync(FULL, cr3, o);
                ci3 += __shfl_down_sync(FULL, ci3, o);
            }
            if (lane == 0) {
                float kx = mx * ax, ky = my * ay;
                float kxy2 = kx * kx + ky * ky;
                float kz, k2, qg;
                kz = mz0 * az;                 k2 = kxy2 + kz * kz;
                qg = __expf(-K2FAC_F * k2) * __frcp_rn(k2);
                blockAcc = fmaf(G.w0 * qg, fmaf(cr0, cr0, ci0 * ci0), blockAcc);
                kz = (mz0 + 1.f) * az;         k2 = kxy2 + kz * kz;
                qg = __expf(-K2FAC_F * k2) * __frcp_rn(k2);
                blockAcc = fmaf(G.w1 * qg, fmaf(cr1, cr1, ci1 * ci1), blockAcc);
                kz = (mz0 + 2.f) * az;         k2 = kxy2 + kz * kz;
                qg = __expf(-K2FAC_F * k2) * __frcp_rn(k2);
                blockAcc = fmaf(G.w2 * qg, fmaf(cr2, cr2, ci2 * ci2), blockAcc);
                kz = (mz0 + 3.f) * az;         k2 = kxy2 + kz * kz;
                qg = __expf(-K2FAC_F * k2) * __frcp_rn(k2);
                blockAcc = fmaf(G.w3 * qg, fmaf(cr3, cr3, ci3 * ci3), blockAcc);
            }
        }
        if (lane == 0)
            g_recip_part[(j * 8 + warp) * NUM_BATCH + b] = blockAcc;   // plain store
    }
}

// ------------------------------------------------------------------
// finalize: 128 blocks x 128 threads (4 blocks per batch). Warp 0 of
// each block sums the 64 recip partials of its batch; elementwise
// combine. g_ereal reset by its reader (zero invariant for replays).
// ------------------------------------------------------------------
__global__ void k_final(const float* __restrict__ Qa,
                        const float* __restrict__ cell,
                        float* __restrict__ out) {
    int n = blockIdx.x * 128 + threadIdx.x;
    int b = n >> 9;                 // same for whole block (128 | 512)
    int a = threadIdx.x;
    __shared__ float srec;

    float er = g_ereal[n];
    g_ereal[n] = 0.0f;              // restore invariant for next replay

    if (a < 32) {
        float t = 0.0f;
#pragma unroll
        for (int m = 0; m < PPB / 32; m++)
            t += g_recip_part[(a + m * 32) * NUM_BATCH + b];
#pragma unroll
        for (int o = 16; o > 0; o >>= 1) t += __shfl_down_sync(FULL, t, o);
        if (a == 0) srec = t;
    }
    __syncthreads();
    float rec = srec;

    float q = Qa[n];
    float q2 = q * q;
    float w = q2 + EPS_F;
    float wnorm = g_wnorm[b];

    float Lx = cell[b * 9 + 0];
    float Ly = cell[b * 9 + 4];
    float Lz = cell[b * 9 + 8];
    float erec = (w / wnorm) * (TWO_PI_F / (Lx * Ly * Lz)) * rec;
    out[n] = er + erec - SELF_F * q2;
}

// ------------------------------------------------------------------
extern "C" void kernel_launch(void* const* d_in, const int* in_sizes, int n_in,
                              void* d_out, int out_size) {
    const float* Qa    = (const float*)d_in[0];
    const float* rij   = (const float*)d_in[1];
    const float* R     = (const float*)d_in[2];
    const float* cell  = (const float*)d_in[3];
    const int*   idx_i = (const int*)d_in[5];
    const int*   idx_j = (const int*)d_in[6];
    float* out = (float*)d_out;

    k_main<<<TOTAL_BLOCKS, 256>>>(Qa, rij, idx_i, idx_j, R, cell);
    k_final<<<N_ATOMS / 128, 128>>>(Qa, cell, out);
}

// round 14
// speedup vs baseline: 1.4629x; 1.0755x over previous
#include <cuda_runtime.h>
#include <cuda_bf16.h>
#include <math.h>

// ---- static problem config (matches reference) ----
#define N_ATOMS 16384
#define NUM_BATCH 32
#define ATOMS_PER_BATCH 512
#define N_PAIRS 1048576

#define ALPHA_F       0.401f            // 4/10 + 0.001
#define K2FAC_F       1.5547167f        // 0.25 / ALPHA^2
#define TWO_PI_F      6.283185307179586f
#define SELF_F        0.2262400229976503f   // ALPHA / sqrt(pi)
#define EPS_F         1e-8f
#define FULL 0xFFFFFFFFu

#define REAL_BLOCKS 512                 // 512 blocks * 8 warps * 256 pairs = 1M
#define PAIRS_PER_WARP 256
#define KMAXI 8

// ------------------------------------------------------------------
// Compile-time k-table organized as GROUPS of 4 consecutive mz within
// one (mx,my) column of the canonical half lattice. A warp computes one
// sincos for the first entry of a group and derives the other three by
// complex rotation with the per-atom phasor e^{i*theta_z}.
// canonical: mx>0 | (mx=0 & my>0) | (mx=0 & my=0 & mz>0); 0<|k|^2<=64.
// ------------------------------------------------------------------
struct KGroup { float mx, my, mz0, pad, w0, w1, w2, w3; };

constexpr int ifsqrt(int v) { int r = 0; while ((r + 1) * (r + 1) <= v) r++; return r; }

constexpr int count_groups() {
    int n = 0;
    n += 2;                                        // (0,0): mz 1..8 -> 2 groups
    for (int my = 1; my <= KMAXI; my++) {          // mx=0 columns
        int L = ifsqrt(KMAXI * KMAXI - my * my);
        n += (2 * L + 1 + 3) / 4;
    }
    for (int mx = 1; mx <= KMAXI; mx++) {
        int L2 = ifsqrt(KMAXI * KMAXI - mx * mx);
        for (int my = -L2; my <= L2; my++) {
            int L = ifsqrt(KMAXI * KMAXI - mx * mx - my * my);
            n += (2 * L + 1 + 3) / 4;
        }
    }
    return n;
}
constexpr int NG     = count_groups();
constexpr int NG_PAD = ((NG + 79) / 80) * 80;      // multiple of 80 -> KBg mult of 10
constexpr int KBg    = NG_PAD / 8;                 // chunks of 8 groups
constexpr int JG     = 10;                         // chunk groups per batch
static_assert(KBg % JG == 0, "balanced chunks");
constexpr int CHUNKS_PER_BLOCK = KBg / JG;

struct KGTable { KGroup g[NG_PAD]; };

constexpr KGTable make_kg() {
    KGTable t{};
    int n = 0;
    // (0,0): mz 1..8
    for (int mz0 = 1; mz0 <= 8; mz0 += 4) {
        t.g[n].mx = 0.f; t.g[n].my = 0.f; t.g[n].mz0 = (float)mz0; t.g[n].pad = 0.f;
        t.g[n].w0 = (mz0 + 0 <= 8) ? 2.f : 0.f;
        t.g[n].w1 = (mz0 + 1 <= 8) ? 2.f : 0.f;
        t.g[n].w2 = (mz0 + 2 <= 8) ? 2.f : 0.f;
        t.g[n].w3 = (mz0 + 3 <= 8) ? 2.f : 0.f;
        n++;
    }
    for (int my = 1; my <= KMAXI; my++) {
        int L = ifsqrt(KMAXI * KMAXI - my * my);
        for (int mz0 = -L; mz0 <= L; mz0 += 4) {
            t.g[n].mx = 0.f; t.g[n].my = (float)my; t.g[n].mz0 = (float)mz0; t.g[n].pad = 0.f;
            t.g[n].w0 = (mz0 + 0 <= L) ? 2.f : 0.f;
            t.g[n].w1 = (mz0 + 1 <= L) ? 2.f : 0.f;
            t.g[n].w2 = (mz0 + 2 <= L) ? 2.f : 0.f;
            t.g[n].w3 = (mz0 + 3 <= L) ? 2.f : 0.f;
            n++;
        }
    }
    for (int mx = 1; mx <= KMAXI; mx++) {
        int L2 = ifsqrt(KMAXI * KMAXI - mx * mx);
        for (int my = -L2; my <= L2; my++) {
            int L = ifsqrt(KMAXI * KMAXI - mx * mx - my * my);
            for (int mz0 = -L; mz0 <= L; mz0 += 4) {
                t.g[n].mx = (float)mx; t.g[n].my = (float)my; t.g[n].mz0 = (float)mz0; t.g[n].pad = 0.f;
                t.g[n].w0 = (mz0 + 0 <= L) ? 2.f : 0.f;
                t.g[n].w1 = (mz0 + 1 <= L) ? 2.f : 0.f;
                t.g[n].w2 = (mz0 + 2 <= L) ? 2.f : 0.f;
                t.g[n].w3 = (mz0 + 3 <= L) ? 2.f : 0.f;
                n++;
            }
        }
    }
    // padding groups: weight 0, k2 > 0 for all 4 entries
    for (; n < NG_PAD; n++) {
        t.g[n].mx = 1.f; t.g[n].my = 0.f; t.g[n].mz0 = 0.f; t.g[n].pad = 0.f;
        t.g[n].w0 = 0.f; t.g[n].w1 = 0.f; t.g[n].w2 = 0.f; t.g[n].w3 = 0.f;
    }
    return t;
}
constexpr KGTable h_kg = make_kg();
__constant__ KGTable c_kg = h_kg;

#define WNORM_BLOCKS 32
#define RECIP_BASE   (REAL_BLOCKS + WNORM_BLOCKS)
#define RECIP_BLOCKS (NUM_BATCH * JG)
#define TOTAL_BLOCKS (RECIP_BASE + RECIP_BLOCKS)
#define PPB          (JG * 8)               // partials per batch (80)
#define NPART        (PPB * NUM_BATCH)

// scratch (no allocations). Partials/wnorm overwritten every call;
// g_ereal reset by its reader in k_final (zero invariant for replays).
__device__ float g_recip_part[NPART];
__device__ float g_wnorm[NUM_BATCH];
__device__ float g_ereal[N_ATOMS];

// ------------------------------------------------------------------
// fused main:
//   blocks [0, 512)        real space (coalesced pairs, warp segscan)
//   blocks [512, 544)      per-batch wnorm
//   blocks [544, 544+320)  recip: (batch b, group j). Stage 512 atoms as
//     (tx,ty,tz,q) + phasor (cos tz, sin tz) in SMEM once; loop 4 chunks.
//     Each warp: one k-GROUP per chunk -> 1 sincos + 3 rotations per atom.
// ------------------------------------------------------------------
__global__ void __launch_bounds__(256) k_main(
        const float* __restrict__ Qa,
        const float* __restrict__ rij,
        const int*   __restrict__ idx_i,
        const int*   __restrict__ idx_j,
        const float* __restrict__ R,
        const float* __restrict__ cell) {
    int bid = blockIdx.x;
    int tid = threadIdx.x;
    int warp = tid >> 5;
    int lane = tid & 31;

    if (bid < REAL_BLOCKS) {
        // ---------------- real space ----------------
        int gw = bid * 8 + warp;
        int base = gw * PAIRS_PER_WARP;
#pragma unroll
        for (int it = 0; it < PAIRS_PER_WARP / 32; it++) {
            int p = base + it * 32 + lane;          // coalesced
            int ii = idx_i[p];
            int jj = idx_j[p];
            float rr = rij[p];
            float fac = __ldg(&Qa[ii]) * __ldg(&Qa[jj]);

            // C-inf switch, fast path
            float x = (rr - 2.5f) * 0.2f;
            float f;
            if (x <= 0.0f)      f = 1.0f;
            else if (x >= 1.0f) f = 0.0f;
            else {
                float fp = __expf(-__frcp_rn(x));
                float fm = __expf(-__frcp_rn(1.0f - x));
                f = fm * __frcp_rn(fp + fm);
            }
            float damped = rsqrtf(fmaf(rr, rr, 1.0f));
            float coul = __frcp_rn(rr);

            // erfc via Abramowitz-Stegun 7.1.26 (abs err <= 1.5e-7)
            float xa = ALPHA_F * rr;
            float t = __frcp_rn(fmaf(0.3275911f, xa, 1.0f));
            float poly = t * fmaf(t, fmaf(t, fmaf(t, fmaf(t, 1.061405429f,
                                -1.453152027f), 1.421413741f),
                                -0.284496736f), 0.254829592f);
            float er = poly * __expf(-xa * xa);

            float pw = fac * (f * damped + (1.0f - f) * coul) * er;

            // warp segmented reduction over sorted ii
            int prev = __shfl_up_sync(FULL, ii, 1);
            bool head = (lane == 0) || (ii != prev);
            unsigned hm = __ballot_sync(FULL, head);
            unsigned below = hm & (0xFFFFFFFFu >> (31 - lane));
            int hp = 31 - __clz(below);
            float s = pw;
#pragma unroll
            for (int d = 1; d < 32; d <<= 1) {
                float v = __shfl_up_sync(FULL, s, d);
                if (lane >= hp + d) s += v;
            }
            bool lastv = (lane == 31) || ((hm >> (lane + 1)) & 1u);
            if (lastv) atomicAdd(&g_ereal[ii], s);
        }
    } else if (bid < RECIP_BASE) {
        // ---------------- per-batch wnorm (overwrite) ----------------
        int b = bid - REAL_BLOCKS;
        __shared__ float sw[8];
        float acc = 0.0f;
        for (int a = tid; a < ATOMS_PER_BATCH; a += 256) {
            float q = Qa[b * ATOMS_PER_BATCH + a];
            acc = fmaf(q, q, acc + EPS_F);
        }
#pragma unroll
        for (int o = 16; o > 0; o >>= 1) acc += __shfl_down_sync(FULL, acc, o);
        if (lane == 0) sw[warp] = acc;
        __syncthreads();
        if (tid == 0) {
            float tot = 0.0f;
#pragma unroll
            for (int w2 = 0; w2 < 8; w2++) tot += sw[w2];
            g_wnorm[b] = tot;
        }
    } else {
        // ---------------- reciprocal space (column recursion) ----------------
        int idx = bid - RECIP_BASE;
        int b = idx & (NUM_BATCH - 1);          // batch
        int j = idx >> 5;                       // chunk group 0..JG-1

        __shared__ float4 sA[ATOMS_PER_BATCH];  // (tx, ty, tz, q)
        __shared__ float2 sE[ATOMS_PER_BATCH];  // (cos tz, sin tz)

        float ax = TWO_PI_F * __frcp_rn(cell[b * 9 + 0]);
        float ay = TWO_PI_F * __frcp_rn(cell[b * 9 + 4]);
        float az = TWO_PI_F * __frcp_rn(cell[b * 9 + 8]);

        for (int a = tid; a < ATOMS_PER_BATCH; a += 256) {
            int n = b * ATOMS_PER_BATCH + a;
            float4 v;
            v.x = R[n * 3 + 0] * ax;
            v.y = R[n * 3 + 1] * ay;
            v.z = R[n * 3 + 2] * az;
            v.w = Qa[n];
            sA[a] = v;
            float cz, sz;
            __sincosf(v.z, &sz, &cz);
            sE[a] = make_float2(cz, sz);
        }
        __syncthreads();

        float blockAcc = 0.0f;                  // lane0 accumulator across chunks

#pragma unroll
        for (int c = 0; c < CHUNKS_PER_BLOCK; c++) {
            int grp = (j + c * JG) * 8 + warp;  // one group per warp per chunk
            const KGroup& G = c_kg.g[grp];
            float mx = G.mx, my = G.my, mz0 = G.mz0;

            float cr0 = 0.f, ci0 = 0.f, cr1 = 0.f, ci1 = 0.f;
            float cr2 = 0.f, ci2 = 0.f, cr3 = 0.f, ci3 = 0.f;

#pragma unroll 4
            for (int a = lane; a < ATOMS_PER_BATCH; a += 32) {
                float4 v = sA[a];
                float2 ez = sE[a];
                float q = v.w;
                float dxy = fmaf(mx, v.x, my * v.y);
                float d0 = fmaf(mz0, v.z, dxy);
                float s0, c0;
                __sincosf(d0, &s0, &c0);
                cr0 = fmaf(q, c0, cr0); ci0 = fmaf(q, s0, ci0);
                float c1 = fmaf(c0, ez.x, -s0 * ez.y);
                float s1 = fmaf(s0, ez.x,  c0 * ez.y);
                cr1 = fmaf(q, c1, cr1); ci1 = fmaf(q, s1, ci1);
                float c2 = fmaf(c1, ez.x, -s1 * ez.y);
                float s2 = fmaf(s1, ez.x,  c1 * ez.y);
                cr2 = fmaf(q, c2, cr2); ci2 = fmaf(q, s2, ci2);
                float c3 = fmaf(c2, ez.x, -s2 * ez.y);
                float s3 = fmaf(s2, ez.x,  c2 * ez.y);
                cr3 = fmaf(q, c3, cr3); ci3 = fmaf(q, s3, ci3);
            }
#pragma unroll
            for (int o = 16; o > 0; o >>= 1) {
                cr0 += __shfl_down_sync(FULL, cr0, o);
                ci0 += __shfl_down_sync(FULL, ci0, o);
                cr1 += __shfl_down_sync(FULL, cr1, o);
                ci1 += __shfl_down_sync(FULL, ci1, o);
                cr2 += __shfl_down_sync(FULL, cr2, o);
                ci2 += __shfl_down_sync(FULL, ci2, o);
                cr3 += __shfl_down_sync(FULL, cr3, o);
                ci3 += __shfl_down_sync(FULL, ci3, o);
            }
            if (lane == 0) {
                float kx = mx * ax, ky = my * ay;
                float kxy2 = kx * kx + ky * ky;
                float kz, k2, qg;
                kz = mz0 * az;                 k2 = kxy2 + kz * kz;
                qg = __expf(-K2FAC_F * k2) * __frcp_rn(k2);
                blockAcc = fmaf(G.w0 * qg, fmaf(cr0, cr0, ci0 * ci0), blockAcc);
                kz = (mz0 + 1.f) * az;         k2 = kxy2 + kz * kz;
                qg = __expf(-K2FAC_F * k2) * __frcp_rn(k2);
                blockAcc = fmaf(G.w1 * qg, fmaf(cr1, cr1, ci1 * ci1), blockAcc);
                kz = (mz0 + 2.f) * az;         k2 = kxy2 + kz * kz;
                qg = __expf(-K2FAC_F * k2) * __frcp_rn(k2);
                blockAcc = fmaf(G.w2 * qg, fmaf(cr2, cr2, ci2 * ci2), blockAcc);
                kz = (mz0 + 3.f) * az;         k2 = kxy2 + kz * kz;
                qg = __expf(-K2FAC_F * k2) * __frcp_rn(k2);
                blockAcc = fmaf(G.w3 * qg, fmaf(cr3, cr3, ci3 * ci3), blockAcc);
            }
        }
        if (lane == 0)
            g_recip_part[(j * 8 + warp) * NUM_BATCH + b] = blockAcc;   // plain store
    }
}

// ------------------------------------------------------------------
// finalize: launched with PDL (programmatic stream serialization) so
// its launch/ramp overlaps k_main's tail; cudaGridDependencySynchronize
// orders it after all k_main memory. 128 blocks x 128 threads.
// g_ereal reset by its reader (zero invariant for replays).
// ------------------------------------------------------------------
__global__ void k_final(const float* __restrict__ Qa,
                        const float* __restrict__ cell,
                        float* __restrict__ out) {
#if __CUDA_ARCH__ >= 900
    cudaGridDependencySynchronize();
#endif
    int n = blockIdx.x * 128 + threadIdx.x;
    int b = n >> 9;                 // same for whole block (128 | 512)
    int a = threadIdx.x;
    __shared__ float srec;

    float er = g_ereal[n];
    g_ereal[n] = 0.0f;              // restore invariant for next replay

    if (a < 32) {
        float t = 0.0f;
        for (int p = a; p < PPB; p += 32)
            t += g_recip_part[p * NUM_BATCH + b];
#pragma unroll
        for (int o = 16; o > 0; o >>= 1) t += __shfl_down_sync(FULL, t, o);
        if (a == 0) srec = t;
    }
    __syncthreads();
    float rec = srec;

    float q = Qa[n];
    float q2 = q * q;
    float w = q2 + EPS_F;
    float wnorm = g_wnorm[b];

    float Lx = cell[b * 9 + 0];
    float Ly = cell[b * 9 + 4];
    float Lz = cell[b * 9 + 8];
    float erec = (w / wnorm) * (TWO_PI_F / (Lx * Ly * Lz)) * rec;
    out[n] = er + erec - SELF_F * q2;
}

// ------------------------------------------------------------------
extern "C" void kernel_launch(void* const* d_in, const int* in_sizes, int n_in,
                              void* d_out, int out_size) {
    const float* Qa    = (const float*)d_in[0];
    const float* rij   = (const float*)d_in[1];
    const float* R     = (const float*)d_in[2];
    const float* cell  = (const float*)d_in[3];
    const int*   idx_i = (const int*)d_in[5];
    const int*   idx_j = (const int*)d_in[6];
    float* out = (float*)d_out;

    k_main<<<TOTAL_BLOCKS, 256>>>(Qa, rij, idx_i, idx_j, R, cell);

    // k_final with programmatic dependent launch: overlap its launch/ramp
    // with k_main's tail; the in-kernel grid sync enforces ordering.
    cudaLaunchConfig_t cfg = {};
    cfg.gridDim  = dim3(N_ATOMS / 128);
    cfg.blockDim = dim3(128);
    cfg.dynamicSmemBytes = 0;
    cfg.stream = 0;
    cudaLaunchAttribute attrs[1];
    attrs[0].id = cudaLaunchAttributeProgrammaticStreamSerialization;
    attrs[0].val.programmaticStreamSerializationAllowed = 1;
    cfg.attrs = attrs;
    cfg.numAttrs = 1;
    cudaError_t e = cudaLaunchKernelEx(&cfg, k_final, Qa, cell, out);
    if (e != cudaSuccess) {
        // fallback: plain launch (ordering via stream)
        k_final<<<N_ATOMS / 128, 128>>>(Qa, cell, out);
    }
}